// round 4
// baseline (speedup 1.0000x reference)
#include <cuda_runtime.h>
#include <math.h>

// Problem constants
#define BB    2
#define NN    2048
#define IND   256
#define DIMV  256
#define HH    8
#define DHH   32
#define ROWS  (BB*NN)          // 4096
#define TEMP  0.17677669529663687f  // fp32(1/sqrt(32))

#define MSG_OFF   0
#define SCORE_OFF 1048576       // ROWS*DIMV
#define IDX_OFF   1179648       // SCORE_OFF + ROWS*4*8

// Scratch (static device memory; no allocations allowed)
__device__ float g_xn [ROWS*IND];
__device__ float g_q  [ROWS*DIMV];   // layout [b][h][s][d]
__device__ float g_k  [ROWS*DIMV];   // layout [b][h][s][d]
__device__ float g_v  [ROWS*DIMV];   // layout [b][h][s][d]
__device__ float g_msg[ROWS*DIMV];   // layout [row][dim]

typedef unsigned long long ull;

__device__ __forceinline__ ull fma2(ull a, ull b, ull c) {
    ull d; asm("fma.rn.f32x2 %0,%1,%2,%3;" : "=l"(d) : "l"(a), "l"(b), "l"(c)); return d;
}
__device__ __forceinline__ ull pack2(float x) {
    ull d; unsigned u = __float_as_uint(x);
    asm("mov.b64 %0,{%1,%1};" : "=l"(d) : "r"(u)); return d;
}
__device__ __forceinline__ ull pack_ab(float a, float b) {
    ull d; asm("mov.b64 %0,{%1,%2};" : "=l"(d)
               : "r"(__float_as_uint(a)), "r"(__float_as_uint(b))); return d;
}
__device__ __forceinline__ void unpack2(ull a, float& lo, float& hi) {
    unsigned x, y; asm("mov.b64 {%0,%1},%2;" : "=r"(x), "=r"(y) : "l"(a));
    lo = __uint_as_float(x); hi = __uint_as_float(y);
}

// ---------------------------------------------------------------------------
// 1) LayerNorm (unchanged — exactness-critical path)
// ---------------------------------------------------------------------------
__global__ void ln_kernel(const float* __restrict__ x,
                          const float* __restrict__ gam,
                          const float* __restrict__ bet) {
    __shared__ float red[8];
    int row = blockIdx.x, tid = threadIdx.x;
    int w = tid >> 5, ln = tid & 31;
    float v = x[row*IND + tid];

    float s = v;
#pragma unroll
    for (int o = 16; o > 0; o >>= 1) s += __shfl_xor_sync(0xffffffffu, s, o);
    if (ln == 0) red[w] = s;
    __syncthreads();
    float S = 0.f;
#pragma unroll
    for (int i = 0; i < 8; i++) S += red[i];
    float mu = S * (1.0f/IND);

    float d  = v - mu;
    float q  = d * d;
    __syncthreads();
#pragma unroll
    for (int o = 16; o > 0; o >>= 1) q += __shfl_xor_sync(0xffffffffu, q, o);
    if (ln == 0) red[w] = q;
    __syncthreads();
    float Q = 0.f;
#pragma unroll
    for (int i = 0; i < 8; i++) Q += red[i];
    float var = Q * (1.0f/IND);

    float denom = __fsqrt_rn(var + 1e-5f);
    float xh    = __fdiv_rn(d, denom);
    g_xn[row*IND + tid] = xh * gam[tid] + bet[tid];
}

// ---------------------------------------------------------------------------
// 2) QKV GEMM (unchanged): 64x128 tile, FFMA2 col pairs.
// ---------------------------------------------------------------------------
__global__ void __launch_bounds__(256) qkv_gemm(const float* __restrict__ W) {
    __shared__ float As[32][68];
    __shared__ ull   Bs2[32][66];
    int tid = threadIdx.x;
    int r0 = blockIdx.y * 64, n0 = blockIdx.x * 128;
    int tx = tid & 15, ty = tid >> 4;
    float* Bf = (float*)Bs2;

    ull c2[4][4];
#pragma unroll
    for (int i = 0; i < 4; i++)
#pragma unroll
        for (int u = 0; u < 4; u++) c2[i][u] = 0ull;

    for (int k0 = 0; k0 < 256; k0 += 32) {
#pragma unroll
        for (int r = 0; r < 2; r++) {
            int f = tid + 256*r;
            int m = f >> 3, k4 = (f & 7) << 2;
            float4 a = *(const float4*)&g_xn[(r0+m)*256 + k0 + k4];
            As[k4+0][m]=a.x; As[k4+1][m]=a.y; As[k4+2][m]=a.z; As[k4+3][m]=a.w;
        }
#pragma unroll
        for (int r = 0; r < 4; r++) {
            int f = tid + 256*r;
            int m = f >> 3, k4 = (f & 7) << 2;
            float4 b = *(const float4*)&W[(n0+m)*256 + k0 + k4];
            Bf[(k4+0)*132+m]=b.x; Bf[(k4+1)*132+m]=b.y;
            Bf[(k4+2)*132+m]=b.z; Bf[(k4+3)*132+m]=b.w;
        }
        __syncthreads();
#pragma unroll
        for (int kk = 0; kk < 32; kk++) {
            float4 a = *(const float4*)&As[kk][ty*4];
            ull ap0 = pack2(a.x), ap1 = pack2(a.y), ap2 = pack2(a.z), ap3 = pack2(a.w);
#pragma unroll
            for (int u = 0; u < 4; u++) {
                ull b = Bs2[kk][tx + 16*u];
                c2[0][u] = fma2(ap0, b, c2[0][u]);
                c2[1][u] = fma2(ap1, b, c2[1][u]);
                c2[2][u] = fma2(ap2, b, c2[2][u]);
                c2[3][u] = fma2(ap3, b, c2[3][u]);
            }
        }
        __syncthreads();
    }
#pragma unroll
    for (int i = 0; i < 4; i++)
#pragma unroll
        for (int u = 0; u < 4; u++) {
            float lo, hi; unpack2(c2[i][u], lo, hi);
            int row = r0 + ty*4 + i;
            int col = n0 + 2*(tx + 16*u);
            int which = col >> 8, h = (col >> 5) & 7, d = col & 31;
            int b = row >> 11, s = row & 2047;
            float* dst = (which == 0) ? g_q : ((which == 1) ? g_k : g_v);
            float2* p = (float2*)&dst[(((b<<3)+h)*2048 + s)*32 + d];
            *p = make_float2(lo, hi);
        }
}

// ---------------------------------------------------------------------------
// 3) Attention: two-phase tiled. Block = 128 threads, 64 queries, one (b,h).
//    Phase A: scores with 2-QUERY f32x2 lane packing (each lane strict
//    sequential ascending-d fp32 chain = bit-identical to scalar) -> exp to
//    smem E. Phase B: PV as a register-tiled GEMM over E,V (16 acc regs).
//    Top-4/Z tracked per key-quarter thread; exact merge at the end.
// ---------------------------------------------------------------------------
#define QB 64
#define KT 32

__global__ void __launch_bounds__(128, 3) attn_kernel(float* __restrict__ out) {
    __shared__ ull   Kdup[KT][32];    // Kdup[j][d] = {k,k}          (8 KB)
    __shared__ float Vs  [KT][32];    //                              (4 KB)
    __shared__ float Es  [KT][68];    // Es[j][q], padded             (8.5 KB)
    __shared__ float Macc[QB][34];    // final acc dump               (8.7 KB)
    __shared__ float Tsm [QB][16];    // topk scores (4 quarters x 4) (4 KB)
    __shared__ int   Ism [QB][16];    // topk indices                 (4 KB)
    __shared__ float Zsm [QB][4];     // partial Z                    (1 KB)

    int bid  = blockIdx.x;            // 512 blocks
    int bh   = bid & 15;
    int qblk = bid >> 4;              // 0..31
    int b    = bh >> 3, h = bh & 7;
    int tid  = threadIdx.x;

    // phase-A mapping: query pair m (queries 2m,2m+1), key quarter
    int m = tid & 31, quarter = tid >> 5;
    // phase-B mapping: 4 queries x 4 dims
    int qg = tid & 15, dg = tid >> 4;

    // load q pair, packed {qA[d], qB[d]}
    ull qp2[32];
    {
        const float4* qa = (const float4*)(g_q + ((size_t)bh*2048 + qblk*64 + 2*m)*32);
        const float4* qb = qa + 8;
#pragma unroll
        for (int c = 0; c < 8; c++) {
            float4 fa = qa[c], fb = qb[c];
            qp2[4*c+0] = pack_ab(fa.x, fb.x);
            qp2[4*c+1] = pack_ab(fa.y, fb.y);
            qp2[4*c+2] = pack_ab(fa.z, fb.z);
            qp2[4*c+3] = pack_ab(fa.w, fb.w);
        }
    }

    ull acc2[4][2];
#pragma unroll
    for (int i = 0; i < 4; i++) { acc2[i][0] = 0ull; acc2[i][1] = 0ull; }

    float ZA = 0.f, ZB = 0.f;
    float tA0=-3e38f,tA1=-3e38f,tA2=-3e38f,tA3=-3e38f;
    float tB0=-3e38f,tB1=-3e38f,tB2=-3e38f,tB3=-3e38f;
    int   iA0=0,iA1=0,iA2=0,iA3=0, iB0=0,iB1=0,iB2=0,iB3=0;

    const float* kbase = g_k + (size_t)bh*65536;
    const float* vbase = g_v + (size_t)bh*65536;

    for (int t0 = 0; t0 < 2048; t0 += KT) {
        // ---- cooperative load K (duplicated) and V ----
        {
            int j = tid >> 2, o = tid & 3;           // key j, d-octet o
            const float4* kr = (const float4*)(kbase + (size_t)(t0 + j)*32 + o*8);
            float4 k1 = kr[0], k2 = kr[1];
            ull* kd = &Kdup[j][o*8];
            kd[0]=pack2(k1.x); kd[1]=pack2(k1.y); kd[2]=pack2(k1.z); kd[3]=pack2(k1.w);
            kd[4]=pack2(k2.x); kd[5]=pack2(k2.y); kd[6]=pack2(k2.z); kd[7]=pack2(k2.w);
            const float4* vr = (const float4*)(vbase + (size_t)(t0 + j)*32 + o*8);
            *(float4*)&Vs[j][o*8]   = vr[0];
            *(float4*)&Vs[j][o*8+4] = vr[1];
        }
        __syncthreads();

        // ---- phase A: scores for 8 keys (this quarter), 2 queries/thread ----
#pragma unroll
        for (int jp = 0; jp < 8; jp += 2) {
            int j0 = quarter*8 + jp, j1 = j0 + 1;
            const ulonglong2* ka = (const ulonglong2*)&Kdup[j0][0];
            const ulonglong2* kb = (const ulonglong2*)&Kdup[j1][0];
            ull s0 = 0ull, s1 = 0ull;
#pragma unroll
            for (int u = 0; u < 16; u++) {
                ulonglong2 a = ka[u], c = kb[u];
                s0 = fma2(qp2[2*u],   a.x, s0);
                s1 = fma2(qp2[2*u],   c.x, s1);
                s0 = fma2(qp2[2*u+1], a.y, s0);
                s1 = fma2(qp2[2*u+1], c.y, s1);
            }
            float sA0, sB0, sA1, sB1;
            unpack2(s0, sA0, sB0); unpack2(s1, sA1, sB1);
            sA0 *= TEMP; sB0 *= TEMP; sA1 *= TEMP; sB1 *= TEMP;

            float eA0 = __expf(sA0), eB0 = __expf(sB0);
            float eA1 = __expf(sA1), eB1 = __expf(sB1);
            ZA += eA0; ZB += eB0;
            *(float2*)&Es[j0][2*m] = make_float2(eA0, eB0);
            ZA += eA1; ZB += eB1;
            *(float2*)&Es[j1][2*m] = make_float2(eA1, eB1);

            // top-4 updates, ascending key order per query
            int s;
            s = t0 + j0;
            if (sA0 > tA3) {
                if (sA0 > tA1) {
                    if (sA0 > tA0) { tA3=tA2;iA3=iA2; tA2=tA1;iA2=iA1; tA1=tA0;iA1=iA0; tA0=sA0;iA0=s; }
                    else           { tA3=tA2;iA3=iA2; tA2=tA1;iA2=iA1; tA1=sA0;iA1=s; }
                } else {
                    if (sA0 > tA2) { tA3=tA2;iA3=iA2; tA2=sA0;iA2=s; }
                    else           { tA3=sA0;iA3=s; }
                }
            }
            if (sB0 > tB3) {
                if (sB0 > tB1) {
                    if (sB0 > tB0) { tB3=tB2;iB3=iB2; tB2=tB1;iB2=iB1; tB1=tB0;iB1=iB0; tB0=sB0;iB0=s; }
                    else           { tB3=tB2;iB3=iB2; tB2=tB1;iB2=iB1; tB1=sB0;iB1=s; }
                } else {
                    if (sB0 > tB2) { tB3=tB2;iB3=iB2; tB2=sB0;iB2=s; }
                    else           { tB3=sB0;iB3=s; }
                }
            }
            s = t0 + j1;
            if (sA1 > tA3) {
                if (sA1 > tA1) {
                    if (sA1 > tA0) { tA3=tA2;iA3=iA2; tA2=tA1;iA2=iA1; tA1=tA0;iA1=iA0; tA0=sA1;iA0=s; }
                    else           { tA3=tA2;iA3=iA2; tA2=tA1;iA2=iA1; tA1=sA1;iA1=s; }
                } else {
                    if (sA1 > tA2) { tA3=tA2;iA3=iA2; tA2=sA1;iA2=s; }
                    else           { tA3=sA1;iA3=s; }
                }
            }
            if (sB1 > tB3) {
                if (sB1 > tB1) {
                    if (sB1 > tB0) { tB3=tB2;iB3=iB2; tB2=tB1;iB2=iB1; tB1=tB0;iB1=iB0; tB0=sB1;iB0=s; }
                    else           { tB3=tB2;iB3=iB2; tB2=tB1;iB2=iB1; tB1=sB1;iB1=s; }
                } else {
                    if (sB1 > tB2) { tB3=tB2;iB3=iB2; tB2=sB1;iB2=s; }
                    else           { tB3=sB1;iB3=s; }
                }
            }
        }
        __syncthreads();

        // ---- phase B: acc[4q][4d] += E * V over 32 keys ----
#pragma unroll 4
        for (int j = 0; j < KT; j++) {
            float4 e4 = *(const float4*)&Es[j][qg*4];
            float4 v4 = *(const float4*)&Vs[j][dg*4];
            ull vlo = pack_ab(v4.x, v4.y), vhi = pack_ab(v4.z, v4.w);
            ull e0 = pack2(e4.x), e1 = pack2(e4.y), e2 = pack2(e4.z), e3 = pack2(e4.w);
            acc2[0][0] = fma2(e0, vlo, acc2[0][0]); acc2[0][1] = fma2(e0, vhi, acc2[0][1]);
            acc2[1][0] = fma2(e1, vlo, acc2[1][0]); acc2[1][1] = fma2(e1, vhi, acc2[1][1]);
            acc2[2][0] = fma2(e2, vlo, acc2[2][0]); acc2[2][1] = fma2(e2, vhi, acc2[2][1]);
            acc2[3][0] = fma2(e3, vlo, acc2[3][0]); acc2[3][1] = fma2(e3, vhi, acc2[3][1]);
        }
        __syncthreads();
    }

    // ---- dump acc, topk, Z to smem ----
#pragma unroll
    for (int i = 0; i < 4; i++)
#pragma unroll
        for (int u = 0; u < 2; u++) {
            float lo, hi; unpack2(acc2[i][u], lo, hi);
            *(float2*)&Macc[qg*4 + i][dg*4 + 2*u] = make_float2(lo, hi);
        }
    {
        int qa = 2*m, qb = 2*m + 1, base = quarter*4;
        Tsm[qa][base+0]=tA0; Tsm[qa][base+1]=tA1; Tsm[qa][base+2]=tA2; Tsm[qa][base+3]=tA3;
        Ism[qa][base+0]=iA0; Ism[qa][base+1]=iA1; Ism[qa][base+2]=iA2; Ism[qa][base+3]=iA3;
        Tsm[qb][base+0]=tB0; Tsm[qb][base+1]=tB1; Tsm[qb][base+2]=tB2; Tsm[qb][base+3]=tB3;
        Ism[qb][base+0]=iB0; Ism[qb][base+1]=iB1; Ism[qb][base+2]=iB2; Ism[qb][base+3]=iB3;
        Zsm[qa][quarter] = ZA; Zsm[qb][quarter] = ZB;
    }
    __syncthreads();

    // ---- finalize: one thread per query ----
    if (tid < QB) {
        int q = tid;
        float Z = ((Zsm[q][0] + Zsm[q][1]) + Zsm[q][2]) + Zsm[q][3];

        float ts[4]; int is[4];
#pragma unroll
        for (int r = 0; r < 4; r++) {
            float best = -3.3e38f; int bi = 0x7fffffff; int bslot = 0;
#pragma unroll
            for (int e = 0; e < 16; e++) {
                float sc = Tsm[q][e]; int ix = Ism[q][e];
                if (sc > best || (sc == best && ix < bi)) { best = sc; bi = ix; bslot = e; }
            }
            Tsm[q][bslot] = -3.3e38f;
            ts[r] = best; is[r] = bi;
        }

        float e0 = __expf(ts[0]), e1 = __expf(ts[1]), e2v = __expf(ts[2]), e3 = __expf(ts[3]);
        const float* v0 = g_v + ((size_t)bh*2048 + is[0])*32;
        const float* v1 = g_v + ((size_t)bh*2048 + is[1])*32;
        const float* v2 = g_v + ((size_t)bh*2048 + is[2])*32;
        const float* v3 = g_v + ((size_t)bh*2048 + is[3])*32;

        float rZ = 1.0f / Z;
        float mm[32];
#pragma unroll
        for (int d = 0; d < 32; d++)
            mm[d] = (Macc[q][d] - (e0*v0[d] + e1*v1[d] + e2v*v2[d] + e3*v3[d])) * rZ;

        int l    = qblk*64 + q;
        int rowi = b*2048 + l;
        float* mo = g_msg + (size_t)rowi*256 + h*32;
#pragma unroll
        for (int i = 0; i < 8; i++)
            ((float4*)mo)[i] = make_float4(mm[4*i], mm[4*i+1], mm[4*i+2], mm[4*i+3]);

        float* so = out + SCORE_OFF + rowi*32 + h;
        so[0]  = e0*rZ;  so[8]  = e1*rZ;  so[16] = e2v*rZ; so[24] = e3*rZ;
        float* io = out + IDX_OFF + rowi*32 + h;
        io[0]  = (float)is[0]; io[8]  = (float)is[1];
        io[16] = (float)is[2]; io[24] = (float)is[3];
    }
}

// ---------------------------------------------------------------------------
// 4) Proj GEMM + bias + residual: 64x64 tile, 256 blocks (occupancy-first).
// ---------------------------------------------------------------------------
__global__ void __launch_bounds__(256) proj_gemm(const float* __restrict__ Wp,
                                                 const float* __restrict__ bp,
                                                 float* __restrict__ out) {
    __shared__ float As[32][68];
    __shared__ ull   Bs2[32][34];
    int tid = threadIdx.x;
    int r0 = blockIdx.y * 64, n0 = blockIdx.x * 64;
    int tx = tid & 15, ty = tid >> 4;
    float* Bf = (float*)Bs2;     // row stride 68 floats

    ull c2[4][2];
#pragma unroll
    for (int i = 0; i < 4; i++) { c2[i][0] = 0ull; c2[i][1] = 0ull; }

    for (int k0 = 0; k0 < 256; k0 += 32) {
#pragma unroll
        for (int r = 0; r < 2; r++) {
            int f = tid + 256*r;
            int mrow = f >> 3, k4 = (f & 7) << 2;
            float4 a = *(const float4*)&g_msg[(r0+mrow)*256 + k0 + k4];
            As[k4+0][mrow]=a.x; As[k4+1][mrow]=a.y; As[k4+2][mrow]=a.z; As[k4+3][mrow]=a.w;
        }
        {
            int f = tid;                     // 256 threads cover 64 cols x 4 float4
            int mcol = f >> 2, k4 = (f & 3) << 3;
            float4 b1 = *(const float4*)&Wp[(n0+mcol)*256 + k0 + k4];
            float4 b2 = *(const float4*)&Wp[(n0+mcol)*256 + k0 + k4 + 4];
            Bf[(k4+0)*68+mcol]=b1.x; Bf[(k4+1)*68+mcol]=b1.y;
            Bf[(k4+2)*68+mcol]=b1.z; Bf[(k4+3)*68+mcol]=b1.w;
            Bf[(k4+4)*68+mcol]=b2.x; Bf[(k4+5)*68+mcol]=b2.y;
            Bf[(k4+6)*68+mcol]=b2.z; Bf[(k4+7)*68+mcol]=b2.w;
        }
        __syncthreads();
#pragma unroll
        for (int kk = 0; kk < 32; kk++) {
            float4 a = *(const float4*)&As[kk][ty*4];
            ull ap0 = pack2(a.x), ap1 = pack2(a.y), ap2 = pack2(a.z), ap3 = pack2(a.w);
#pragma unroll
            for (int u = 0; u < 2; u++) {
                ull b = Bs2[kk][tx + 16*u];
                c2[0][u] = fma2(ap0, b, c2[0][u]);
                c2[1][u] = fma2(ap1, b, c2[1][u]);
                c2[2][u] = fma2(ap2, b, c2[2][u]);
                c2[3][u] = fma2(ap3, b, c2[3][u]);
            }
        }
        __syncthreads();
    }
#pragma unroll
    for (int i = 0; i < 4; i++)
#pragma unroll
        for (int u = 0; u < 2; u++) {
            float lo, hi; unpack2(c2[i][u], lo, hi);
            int row = r0 + ty*4 + i;
            int col = n0 + 2*(tx + 16*u);
            int b = row >> 11, l = row & 2047, h = col >> 5, d = col & 31;
            const float* vres = &g_v[(((b<<3)+h)*2048 + l)*32 + d];
            float2 o;
            o.x = lo + bp[col]   + vres[0];
            o.y = hi + bp[col+1] + vres[1];
            *(float2*)&out[row*256 + col] = o;
        }
}

// ---------------------------------------------------------------------------
extern "C" void kernel_launch(void* const* d_in, const int* in_sizes, int n_in,
                              void* d_out, int out_size) {
    const float* points = (const float*)d_in[0];
    const float* gam    = (const float*)d_in[1];
    const float* bet    = (const float*)d_in[2];
    const float* wqkv   = (const float*)d_in[3];
    const float* wproj  = (const float*)d_in[4];
    const float* bproj  = (const float*)d_in[5];
    float* out = (float*)d_out;

    ln_kernel<<<ROWS, 256>>>(points, gam, bet);
    qkv_gemm <<<dim3(6, 64), 256>>>(wqkv);
    attn_kernel<<<512, 128>>>(out);
    proj_gemm<<<dim3(4, 64), 256>>>(wproj, bproj, out);
}

// round 5
// speedup vs baseline: 1.3186x; 1.3186x over previous
#include <cuda_runtime.h>
#include <math.h>

// Problem constants
#define BB    2
#define NN    2048
#define IND   256
#define DIMV  256
#define HH    8
#define DHH   32
#define ROWS  (BB*NN)          // 4096
#define TEMP  0.17677669529663687f  // fp32(1/sqrt(32))

#define MSG_OFF   0
#define SCORE_OFF 1048576       // ROWS*DIMV
#define IDX_OFF   1179648       // SCORE_OFF + ROWS*4*8

#define NSPLIT 2
#define KEYS_PER_SPLIT 1024

// Scratch (static device memory; no allocations allowed)
__device__ float g_xn [ROWS*IND];
__device__ float g_q  [ROWS*DIMV];   // layout [b][h][s][d]
__device__ float g_k  [ROWS*DIMV];   // layout [b][h][s][d]
__device__ float g_v  [ROWS*DIMV];   // layout [b][h][s][d]
__device__ float g_msg[ROWS*DIMV];   // layout [row][dim]
// split-KV partials: index p = (split*16 + bh)*2048 + q
__device__ float g_pacc[NSPLIT*16*2048*32];
__device__ float g_pz  [NSPLIT*16*2048];
__device__ float g_pt  [NSPLIT*16*2048*4];
__device__ int   g_pi  [NSPLIT*16*2048*4];

typedef unsigned long long ull;

__device__ __forceinline__ ull fma2(ull a, ull b, ull c) {
    ull d; asm("fma.rn.f32x2 %0,%1,%2,%3;" : "=l"(d) : "l"(a), "l"(b), "l"(c)); return d;
}
__device__ __forceinline__ ull pack2(float x) {
    ull d; unsigned u = __float_as_uint(x);
    asm("mov.b64 %0,{%1,%1};" : "=l"(d) : "r"(u)); return d;
}
__device__ __forceinline__ void unpack2(ull a, float& lo, float& hi) {
    unsigned x, y; asm("mov.b64 {%0,%1},%2;" : "=r"(x), "=r"(y) : "l"(a));
    lo = __uint_as_float(x); hi = __uint_as_float(y);
}

// ---------------------------------------------------------------------------
// 1) LayerNorm (unchanged — exactness-critical path)
// ---------------------------------------------------------------------------
__global__ void ln_kernel(const float* __restrict__ x,
                          const float* __restrict__ gam,
                          const float* __restrict__ bet) {
    __shared__ float red[8];
    int row = blockIdx.x, tid = threadIdx.x;
    int w = tid >> 5, ln = tid & 31;
    float v = x[row*IND + tid];

    float s = v;
#pragma unroll
    for (int o = 16; o > 0; o >>= 1) s += __shfl_xor_sync(0xffffffffu, s, o);
    if (ln == 0) red[w] = s;
    __syncthreads();
    float S = 0.f;
#pragma unroll
    for (int i = 0; i < 8; i++) S += red[i];
    float mu = S * (1.0f/IND);

    float d  = v - mu;
    float q  = d * d;
    __syncthreads();
#pragma unroll
    for (int o = 16; o > 0; o >>= 1) q += __shfl_xor_sync(0xffffffffu, q, o);
    if (ln == 0) red[w] = q;
    __syncthreads();
    float Q = 0.f;
#pragma unroll
    for (int i = 0; i < 8; i++) Q += red[i];
    float var = Q * (1.0f/IND);

    float denom = __fsqrt_rn(var + 1e-5f);
    float xh    = __fdiv_rn(d, denom);
    g_xn[row*IND + tid] = xh * gam[tid] + bet[tid];
}

// ---------------------------------------------------------------------------
// 2) QKV GEMM (unchanged): 64x128 tile, FFMA2 col pairs.
// ---------------------------------------------------------------------------
__global__ void __launch_bounds__(256) qkv_gemm(const float* __restrict__ W) {
    __shared__ float As[32][68];
    __shared__ ull   Bs2[32][66];
    int tid = threadIdx.x;
    int r0 = blockIdx.y * 64, n0 = blockIdx.x * 128;
    int tx = tid & 15, ty = tid >> 4;
    float* Bf = (float*)Bs2;

    ull c2[4][4];
#pragma unroll
    for (int i = 0; i < 4; i++)
#pragma unroll
        for (int u = 0; u < 4; u++) c2[i][u] = 0ull;

    for (int k0 = 0; k0 < 256; k0 += 32) {
#pragma unroll
        for (int r = 0; r < 2; r++) {
            int f = tid + 256*r;
            int m = f >> 3, k4 = (f & 7) << 2;
            float4 a = *(const float4*)&g_xn[(r0+m)*256 + k0 + k4];
            As[k4+0][m]=a.x; As[k4+1][m]=a.y; As[k4+2][m]=a.z; As[k4+3][m]=a.w;
        }
#pragma unroll
        for (int r = 0; r < 4; r++) {
            int f = tid + 256*r;
            int m = f >> 3, k4 = (f & 7) << 2;
            float4 b = *(const float4*)&W[(n0+m)*256 + k0 + k4];
            Bf[(k4+0)*132+m]=b.x; Bf[(k4+1)*132+m]=b.y;
            Bf[(k4+2)*132+m]=b.z; Bf[(k4+3)*132+m]=b.w;
        }
        __syncthreads();
#pragma unroll
        for (int kk = 0; kk < 32; kk++) {
            float4 a = *(const float4*)&As[kk][ty*4];
            ull ap0 = pack2(a.x), ap1 = pack2(a.y), ap2 = pack2(a.z), ap3 = pack2(a.w);
#pragma unroll
            for (int u = 0; u < 4; u++) {
                ull b = Bs2[kk][tx + 16*u];
                c2[0][u] = fma2(ap0, b, c2[0][u]);
                c2[1][u] = fma2(ap1, b, c2[1][u]);
                c2[2][u] = fma2(ap2, b, c2[2][u]);
                c2[3][u] = fma2(ap3, b, c2[3][u]);
            }
        }
        __syncthreads();
    }
#pragma unroll
    for (int i = 0; i < 4; i++)
#pragma unroll
        for (int u = 0; u < 4; u++) {
            float lo, hi; unpack2(c2[i][u], lo, hi);
            int row = r0 + ty*4 + i;
            int col = n0 + 2*(tx + 16*u);
            int which = col >> 8, h = (col >> 5) & 7, d = col & 31;
            int b = row >> 11, s = row & 2047;
            float* dst = (which == 0) ? g_q : ((which == 1) ? g_k : g_v);
            float2* p = (float2*)&dst[(((b<<3)+h)*2048 + s)*32 + d];
            *p = make_float2(lo, hi);
        }
}

// ---------------------------------------------------------------------------
// 3) Attention (split-KV): one thread per (query, head); block covers 128
//    queries x 1024 keys for one (b,h,split). Key-pair packed scores (each
//    f32x2 lane a strict sequential ascending-d fp32 chain = bit-identical
//    to scalar). Writes unnormalized partials (acc, Z, top-4).
// ---------------------------------------------------------------------------
__global__ void __launch_bounds__(128, 3) attn_kernel() {
    __shared__ ull    Kp[64][34];    // Kp[p][d] = {K[2p][d], K[2p+1][d]}
    __shared__ float4 Vs[128][8];    // xor-swizzled

    int bid   = blockIdx.x;               // 0..511
    int qg    = bid & 15;
    int bh    = (bid >> 4) & 15;
    int split = bid >> 8;                 // 0..1
    int tid   = threadIdx.x;
    int l     = qg*128 + tid;

    // load q, pack each element into both f32x2 lanes
    ull qp[32];
    {
        const float4* qrow = (const float4*)(g_q + ((size_t)bh*2048 + l)*32);
#pragma unroll
        for (int c = 0; c < 8; c++) {
            float4 f = qrow[c];
            qp[4*c+0] = pack2(f.x); qp[4*c+1] = pack2(f.y);
            qp[4*c+2] = pack2(f.z); qp[4*c+3] = pack2(f.w);
        }
    }

    ull acc2[16];
#pragma unroll
    for (int i = 0; i < 16; i++) acc2[i] = 0ull;

    float Z = 0.f;
    float t0 = -3.0e38f, t1 = -3.0e38f, t2 = -3.0e38f, t3 = -3.0e38f;
    int   i0 = 0, i1 = 0, i2 = 0, i3 = 0;

    int kofs = split * KEYS_PER_SPLIT;
    const float4* kb = (const float4*)(g_k + (size_t)bh*65536 + (size_t)kofs*32);
    const float4* vb = (const float4*)(g_v + (size_t)bh*65536 + (size_t)kofs*32);

    for (int s0 = 0; s0 < KEYS_PER_SPLIT; s0 += 128) {
        __syncthreads();
        {
            int j = tid;
            const float4* kg = kb + (size_t)(s0 + j)*8;
            int p = j >> 1, wsel = j & 1;
            unsigned* krow = (unsigned*)&Kp[p][0];
#pragma unroll
            for (int c = 0; c < 8; c++) {
                float4 f = kg[c];
                krow[2*(4*c+0)+wsel] = __float_as_uint(f.x);
                krow[2*(4*c+1)+wsel] = __float_as_uint(f.y);
                krow[2*(4*c+2)+wsel] = __float_as_uint(f.z);
                krow[2*(4*c+3)+wsel] = __float_as_uint(f.w);
            }
            int sw = j & 7;
            const float4* vg = vb + (size_t)(s0 + j)*8;
#pragma unroll
            for (int c = 0; c < 8; c++) Vs[j][c ^ sw] = vg[c];
        }
        __syncthreads();

#pragma unroll 2
        for (int p = 0; p < 64; p++) {
            const ulonglong2* kr = (const ulonglong2*)&Kp[p][0];
            ull sc2 = 0ull;
#pragma unroll
            for (int u = 0; u < 16; u++) {
                ulonglong2 kk = kr[u];
                sc2 = fma2(qp[2*u],   kk.x, sc2);
                sc2 = fma2(qp[2*u+1], kk.y, sc2);
            }
            float sA, sB; unpack2(sc2, sA, sB);
            sA *= TEMP; sB *= TEMP;

            float eA = __expf(sA), eB = __expf(sB);
            Z += eA; Z += eB;
            ull eAp = pack2(eA), eBp = pack2(eB);

            int jA = 2*p, jB = 2*p + 1;
            int swA = jA & 7, swB = jB & 7;
#pragma unroll
            for (int c = 0; c < 8; c++) {
                ulonglong2 va = *(const ulonglong2*)&Vs[jA][c ^ swA];
                acc2[2*c]   = fma2(eAp, va.x, acc2[2*c]);
                acc2[2*c+1] = fma2(eAp, va.y, acc2[2*c+1]);
            }
#pragma unroll
            for (int c = 0; c < 8; c++) {
                ulonglong2 vv = *(const ulonglong2*)&Vs[jB][c ^ swB];
                acc2[2*c]   = fma2(eBp, vv.x, acc2[2*c]);
                acc2[2*c+1] = fma2(eBp, vv.y, acc2[2*c+1]);
            }

            // top-4 (strict >, ascending key order preserves tie rule)
            int s = kofs + s0 + jA;
            if (sA > t3) {
                if (sA > t1) {
                    if (sA > t0) { t3=t2;i3=i2; t2=t1;i2=i1; t1=t0;i1=i0; t0=sA;i0=s; }
                    else         { t3=t2;i3=i2; t2=t1;i2=i1; t1=sA;i1=s; }
                } else {
                    if (sA > t2) { t3=t2;i3=i2; t2=sA;i2=s; }
                    else         { t3=sA;i3=s; }
                }
            }
            s = kofs + s0 + jB;
            if (sB > t3) {
                if (sB > t1) {
                    if (sB > t0) { t3=t2;i3=i2; t2=t1;i2=i1; t1=t0;i1=i0; t0=sB;i0=s; }
                    else         { t3=t2;i3=i2; t2=t1;i2=i1; t1=sB;i1=s; }
                } else {
                    if (sB > t2) { t3=t2;i3=i2; t2=sB;i2=s; }
                    else         { t3=sB;i3=s; }
                }
            }
        }
    }

    // ---- write partials ----
    size_t p = ((size_t)(split*16 + bh))*2048 + l;
    float* pa = g_pacc + p*32;
#pragma unroll
    for (int i = 0; i < 16; i++) {
        float lo, hi; unpack2(acc2[i], lo, hi);
        *(float2*)&pa[2*i] = make_float2(lo, hi);
    }
    g_pz[p] = Z;
    g_pt[p*4+0] = t0; g_pt[p*4+1] = t1; g_pt[p*4+2] = t2; g_pt[p*4+3] = t3;
    g_pi[p*4+0] = i0; g_pi[p*4+1] = i1; g_pi[p*4+2] = i2; g_pi[p*4+3] = i3;
}

// ---------------------------------------------------------------------------
// 3b) Merge: one thread per (bh, q). Exact top-4 merge (split-0 keys have
//     lower indices, so ties prefer split 0 via >=). Finalize message.
// ---------------------------------------------------------------------------
__global__ void __launch_bounds__(256) attn_merge(float* __restrict__ out) {
    int idx = blockIdx.x * 256 + threadIdx.x;     // 0..32767
    int bh  = idx >> 11;
    int q   = idx & 2047;
    int b   = bh >> 3, h = bh & 7;

    size_t p0 = (size_t)bh*2048 + q;
    size_t p1 = (size_t)(16 + bh)*2048 + q;

    float T0[4], T1[4]; int I0[4], I1[4];
#pragma unroll
    for (int r = 0; r < 4; r++) {
        T0[r] = g_pt[p0*4+r]; I0[r] = g_pi[p0*4+r];
        T1[r] = g_pt[p1*4+r]; I1[r] = g_pi[p1*4+r];
    }
    float Z = g_pz[p0] + g_pz[p1];

    float ts[4]; int is[4];
    {
        int a = 0, c = 0;
#pragma unroll
        for (int r = 0; r < 4; r++) {
            float s0 = (a < 4) ? T0[a] : -3.3e38f;
            float s1 = (c < 4) ? T1[c] : -3.3e38f;
            if (s0 >= s1) { ts[r] = s0; is[r] = I0[a]; a++; }
            else          { ts[r] = s1; is[r] = I1[c]; c++; }
        }
    }

    float e0 = __expf(ts[0]), e1 = __expf(ts[1]), e2v = __expf(ts[2]), e3 = __expf(ts[3]);
    const float* v0 = g_v + ((size_t)bh*2048 + is[0])*32;
    const float* v1 = g_v + ((size_t)bh*2048 + is[1])*32;
    const float* v2 = g_v + ((size_t)bh*2048 + is[2])*32;
    const float* v3 = g_v + ((size_t)bh*2048 + is[3])*32;

    const float* a0 = g_pacc + p0*32;
    const float* a1 = g_pacc + p1*32;
    float rZ = 1.0f / Z;

    int rowi = b*2048 + q;
    float* mo = g_msg + (size_t)rowi*256 + h*32;
#pragma unroll
    for (int c = 0; c < 8; c++) {
        float4 x0 = *(const float4*)&a0[4*c];
        float4 x1 = *(const float4*)&a1[4*c];
        float4 w0 = *(const float4*)&v0[4*c];
        float4 w1 = *(const float4*)&v1[4*c];
        float4 w2 = *(const float4*)&v2[4*c];
        float4 w3 = *(const float4*)&v3[4*c];
        float4 o;
        o.x = ((x0.x + x1.x) - (e0*w0.x + e1*w1.x + e2v*w2.x + e3*w3.x)) * rZ;
        o.y = ((x0.y + x1.y) - (e0*w0.y + e1*w1.y + e2v*w2.y + e3*w3.y)) * rZ;
        o.z = ((x0.z + x1.z) - (e0*w0.z + e1*w1.z + e2v*w2.z + e3*w3.z)) * rZ;
        o.w = ((x0.w + x1.w) - (e0*w0.w + e1*w1.w + e2v*w2.w + e3*w3.w)) * rZ;
        ((float4*)mo)[c] = o;
    }

    float* so = out + SCORE_OFF + rowi*32 + h;
    so[0]  = e0*rZ;  so[8]  = e1*rZ;  so[16] = e2v*rZ; so[24] = e3*rZ;
    float* io = out + IDX_OFF + rowi*32 + h;
    io[0]  = (float)is[0]; io[8]  = (float)is[1];
    io[16] = (float)is[2]; io[24] = (float)is[3];
}

// ---------------------------------------------------------------------------
// 4) Proj GEMM + bias + residual: 64x64 tile, 256 blocks.
// ---------------------------------------------------------------------------
__global__ void __launch_bounds__(256) proj_gemm(const float* __restrict__ Wp,
                                                 const float* __restrict__ bp,
                                                 float* __restrict__ out) {
    __shared__ float As[32][68];
    __shared__ ull   Bs2[32][34];
    int tid = threadIdx.x;
    int r0 = blockIdx.y * 64, n0 = blockIdx.x * 64;
    int tx = tid & 15, ty = tid >> 4;
    float* Bf = (float*)Bs2;

    ull c2[4][2];
#pragma unroll
    for (int i = 0; i < 4; i++) { c2[i][0] = 0ull; c2[i][1] = 0ull; }

    for (int k0 = 0; k0 < 256; k0 += 32) {
#pragma unroll
        for (int r = 0; r < 2; r++) {
            int f = tid + 256*r;
            int mrow = f >> 3, k4 = (f & 7) << 2;
            float4 a = *(const float4*)&g_msg[(r0+mrow)*256 + k0 + k4];
            As[k4+0][mrow]=a.x; As[k4+1][mrow]=a.y; As[k4+2][mrow]=a.z; As[k4+3][mrow]=a.w;
        }
        {
            int f = tid;
            int mcol = f >> 2, k4 = (f & 3) << 3;
            float4 b1 = *(const float4*)&Wp[(n0+mcol)*256 + k0 + k4];
            float4 b2 = *(const float4*)&Wp[(n0+mcol)*256 + k0 + k4 + 4];
            Bf[(k4+0)*68+mcol]=b1.x; Bf[(k4+1)*68+mcol]=b1.y;
            Bf[(k4+2)*68+mcol]=b1.z; Bf[(k4+3)*68+mcol]=b1.w;
            Bf[(k4+4)*68+mcol]=b2.x; Bf[(k4+5)*68+mcol]=b2.y;
            Bf[(k4+6)*68+mcol]=b2.z; Bf[(k4+7)*68+mcol]=b2.w;
        }
        __syncthreads();
#pragma unroll
        for (int kk = 0; kk < 32; kk++) {
            float4 a = *(const float4*)&As[kk][ty*4];
            ull ap0 = pack2(a.x), ap1 = pack2(a.y), ap2 = pack2(a.z), ap3 = pack2(a.w);
#pragma unroll
            for (int u = 0; u < 2; u++) {
                ull b = Bs2[kk][tx + 16*u];
                c2[0][u] = fma2(ap0, b, c2[0][u]);
                c2[1][u] = fma2(ap1, b, c2[1][u]);
                c2[2][u] = fma2(ap2, b, c2[2][u]);
                c2[3][u] = fma2(ap3, b, c2[3][u]);
            }
        }
        __syncthreads();
    }
#pragma unroll
    for (int i = 0; i < 4; i++)
#pragma unroll
        for (int u = 0; u < 2; u++) {
            float lo, hi; unpack2(c2[i][u], lo, hi);
            int row = r0 + ty*4 + i;
            int col = n0 + 2*(tx + 16*u);
            int b = row >> 11, l = row & 2047, h = col >> 5, d = col & 31;
            const float* vres = &g_v[(((b<<3)+h)*2048 + l)*32 + d];
            float2 o;
            o.x = lo + bp[col]   + vres[0];
            o.y = hi + bp[col+1] + vres[1];
            *(float2*)&out[row*256 + col] = o;
        }
}

// ---------------------------------------------------------------------------
extern "C" void kernel_launch(void* const* d_in, const int* in_sizes, int n_in,
                              void* d_out, int out_size) {
    const float* points = (const float*)d_in[0];
    const float* gam    = (const float*)d_in[1];
    const float* bet    = (const float*)d_in[2];
    const float* wqkv   = (const float*)d_in[3];
    const float* wproj  = (const float*)d_in[4];
    const float* bproj  = (const float*)d_in[5];
    float* out = (float*)d_out;

    ln_kernel<<<ROWS, 256>>>(points, gam, bet);
    qkv_gemm <<<dim3(6, 64), 256>>>(wqkv);
    attn_kernel<<<512, 128>>>();
    attn_merge<<<128, 256>>>(out);
    proj_gemm<<<dim3(4, 64), 256>>>(wproj, bproj, out);
}

// round 6
// speedup vs baseline: 1.4270x; 1.0822x over previous
#include <cuda_runtime.h>
#include <math.h>

// Problem constants
#define BB    2
#define NN    2048
#define IND   256
#define DIMV  256
#define HH    8
#define DHH   32
#define ROWS  (BB*NN)          // 4096
#define TEMP  0.17677669529663687f  // fp32(1/sqrt(32))

#define MSG_OFF   0
#define SCORE_OFF 1048576       // ROWS*DIMV
#define IDX_OFF   1179648       // SCORE_OFF + ROWS*4*8

// Scratch (static device memory; no allocations allowed)
__device__ float g_xn [ROWS*IND];
__device__ float g_q  [ROWS*DIMV];   // [b][h][s][d]
__device__ float g_kp [16*1024*32*2];// K pair-interleaved: [bh][s/2][d][s&1]
__device__ float g_v  [ROWS*DIMV];   // [b][h][s][d]
__device__ float g_msg[ROWS*DIMV];   // [row][dim]

typedef unsigned long long ull;

__device__ __forceinline__ ull fma2(ull a, ull b, ull c) {
    ull d; asm("fma.rn.f32x2 %0,%1,%2,%3;" : "=l"(d) : "l"(a), "l"(b), "l"(c)); return d;
}
__device__ __forceinline__ ull pack2(float x) {
    ull d; unsigned u = __float_as_uint(x);
    asm("mov.b64 %0,{%1,%1};" : "=l"(d) : "r"(u)); return d;
}
__device__ __forceinline__ void unpack2(ull a, float& lo, float& hi) {
    unsigned x, y; asm("mov.b64 {%0,%1},%2;" : "=r"(x), "=r"(y) : "l"(a));
    lo = __uint_as_float(x); hi = __uint_as_float(y);
}
__device__ __forceinline__ void cp16(unsigned dst, const void* src) {
    asm volatile("cp.async.cg.shared.global [%0], [%1], 16;" :: "r"(dst), "l"(src));
}
__device__ __forceinline__ void cp_commit() {
    asm volatile("cp.async.commit_group;");
}
__device__ __forceinline__ void cp_wait1() {
    asm volatile("cp.async.wait_group 1;");
}

// ---------------------------------------------------------------------------
// 1) LayerNorm (unchanged — exactness-critical path)
// ---------------------------------------------------------------------------
__global__ void ln_kernel(const float* __restrict__ x,
                          const float* __restrict__ gam,
                          const float* __restrict__ bet) {
    __shared__ float red[8];
    int row = blockIdx.x, tid = threadIdx.x;
    int w = tid >> 5, ln = tid & 31;
    float v = x[row*IND + tid];

    float s = v;
#pragma unroll
    for (int o = 16; o > 0; o >>= 1) s += __shfl_xor_sync(0xffffffffu, s, o);
    if (ln == 0) red[w] = s;
    __syncthreads();
    float S = 0.f;
#pragma unroll
    for (int i = 0; i < 8; i++) S += red[i];
    float mu = S * (1.0f/IND);

    float d  = v - mu;
    float q  = d * d;
    __syncthreads();
#pragma unroll
    for (int o = 16; o > 0; o >>= 1) q += __shfl_xor_sync(0xffffffffu, q, o);
    if (ln == 0) red[w] = q;
    __syncthreads();
    float Q = 0.f;
#pragma unroll
    for (int i = 0; i < 8; i++) Q += red[i];
    float var = Q * (1.0f/IND);

    float denom = __fsqrt_rn(var + 1e-5f);
    float xh    = __fdiv_rn(d, denom);
    g_xn[row*IND + tid] = xh * gam[tid] + bet[tid];
}

// ---------------------------------------------------------------------------
// 2) QKV GEMM: 64x128 tile, FFMA2 col pairs. K written pair-interleaved.
// ---------------------------------------------------------------------------
__global__ void __launch_bounds__(256) qkv_gemm(const float* __restrict__ W) {
    __shared__ float As[32][68];
    __shared__ ull   Bs2[32][66];
    int tid = threadIdx.x;
    int r0 = blockIdx.y * 64, n0 = blockIdx.x * 128;
    int tx = tid & 15, ty = tid >> 4;
    float* Bf = (float*)Bs2;

    ull c2[4][4];
#pragma unroll
    for (int i = 0; i < 4; i++)
#pragma unroll
        for (int u = 0; u < 4; u++) c2[i][u] = 0ull;

    for (int k0 = 0; k0 < 256; k0 += 32) {
#pragma unroll
        for (int r = 0; r < 2; r++) {
            int f = tid + 256*r;
            int m = f >> 3, k4 = (f & 7) << 2;
            float4 a = *(const float4*)&g_xn[(r0+m)*256 + k0 + k4];
            As[k4+0][m]=a.x; As[k4+1][m]=a.y; As[k4+2][m]=a.z; As[k4+3][m]=a.w;
        }
#pragma unroll
        for (int r = 0; r < 4; r++) {
            int f = tid + 256*r;
            int m = f >> 3, k4 = (f & 7) << 2;
            float4 b = *(const float4*)&W[(n0+m)*256 + k0 + k4];
            Bf[(k4+0)*132+m]=b.x; Bf[(k4+1)*132+m]=b.y;
            Bf[(k4+2)*132+m]=b.z; Bf[(k4+3)*132+m]=b.w;
        }
        __syncthreads();
#pragma unroll
        for (int kk = 0; kk < 32; kk++) {
            float4 a = *(const float4*)&As[kk][ty*4];
            ull ap0 = pack2(a.x), ap1 = pack2(a.y), ap2 = pack2(a.z), ap3 = pack2(a.w);
#pragma unroll
            for (int u = 0; u < 4; u++) {
                ull b = Bs2[kk][tx + 16*u];
                c2[0][u] = fma2(ap0, b, c2[0][u]);
                c2[1][u] = fma2(ap1, b, c2[1][u]);
                c2[2][u] = fma2(ap2, b, c2[2][u]);
                c2[3][u] = fma2(ap3, b, c2[3][u]);
            }
        }
        __syncthreads();
    }
#pragma unroll
    for (int i = 0; i < 4; i++)
#pragma unroll
        for (int u = 0; u < 4; u++) {
            float lo, hi; unpack2(c2[i][u], lo, hi);
            int row = r0 + ty*4 + i;
            int col = n0 + 2*(tx + 16*u);
            int which = col >> 8, h = (col >> 5) & 7, d = col & 31;
            int b = row >> 11, s = row & 2047;
            int bh = (b<<3) + h;
            if (which == 1) {
                // K: pair-interleaved [bh][s/2][d][s&1]
                float* kp = g_kp + ((((size_t)bh*1024 + (s>>1))*32 + d) << 1) + (s & 1);
                kp[0] = lo; kp[2] = hi;
            } else {
                float* dst = (which == 0) ? g_q : g_v;
                *(float2*)&dst[((size_t)bh*2048 + s)*32 + d] = make_float2(lo, hi);
            }
        }
}

// ---------------------------------------------------------------------------
// 3) Attention: one thread per (query, head), 256 blocks x 128 threads.
//    64-key tiles, 2-stage cp.async double buffering (coalesced bulk copies
//    from the pair-interleaved K layout and row-major V). Scores: f32x2 lanes
//    = two keys, each lane a strict sequential ascending-d fp32 chain
//    (bit-identical to scalar). Inline finalize.
// ---------------------------------------------------------------------------
#define KT 64
#define NTILE (2048/KT)

__global__ void __launch_bounds__(128, 3) attn_kernel(float* __restrict__ out) {
    __shared__ ull   Kp[2][KT/2][32];   // 8 KB per stage
    __shared__ float Vs[2][KT][32];     // 8 KB per stage

    int bid = blockIdx.x;                 // 0..255
    int qg  = bid & 15;
    int bh  = bid >> 4;                   // 0..15
    int b   = bh >> 3, h = bh & 7;
    int tid = threadIdx.x;
    int l   = qg*128 + tid;

    // load q, pack each element into both f32x2 lanes
    ull qp[32];
    {
        const float4* qrow = (const float4*)(g_q + ((size_t)bh*2048 + l)*32);
#pragma unroll
        for (int c = 0; c < 8; c++) {
            float4 f = qrow[c];
            qp[4*c+0] = pack2(f.x); qp[4*c+1] = pack2(f.y);
            qp[4*c+2] = pack2(f.z); qp[4*c+3] = pack2(f.w);
        }
    }

    ull acc2[16];
#pragma unroll
    for (int i = 0; i < 16; i++) acc2[i] = 0ull;

    float Z = 0.f;
    float t0 = -3.0e38f, t1 = -3.0e38f, t2 = -3.0e38f, t3 = -3.0e38f;
    int   i0 = 0, i1 = 0, i2 = 0, i3 = 0;

    const char* kg = (const char*)g_kp + (size_t)bh*262144;  // 64K floats/bh
    const char* vg = (const char*)g_v  + (size_t)bh*262144;

    unsigned kbase0 = (unsigned)__cvta_generic_to_shared(&Kp[0][0][0]);
    unsigned kbase1 = (unsigned)__cvta_generic_to_shared(&Kp[1][0][0]);
    unsigned vbase0 = (unsigned)__cvta_generic_to_shared(&Vs[0][0][0]);
    unsigned vbase1 = (unsigned)__cvta_generic_to_shared(&Vs[1][0][0]);

    // prologue: tile 0 -> stage 0
    {
        const char* ks = kg;  const char* vs = vg;
#pragma unroll
        for (int i = 0; i < 4; i++) {
            int c = tid + i*128;
            cp16(kbase0 + c*16, ks + c*16);
            cp16(vbase0 + c*16, vs + c*16);
        }
        cp_commit();
    }

    for (int t = 0; t < NTILE; t++) {
        int buf = t & 1;
        // prefetch next tile into other stage
        if (t + 1 < NTILE) {
            unsigned kb2 = (buf ? kbase0 : kbase1);
            unsigned vb2 = (buf ? vbase0 : vbase1);
            const char* ks = kg + (size_t)(t+1)*8192;
            const char* vs = vg + (size_t)(t+1)*8192;
#pragma unroll
            for (int i = 0; i < 4; i++) {
                int c = tid + i*128;
                cp16(kb2 + c*16, ks + c*16);
                cp16(vb2 + c*16, vs + c*16);
            }
        }
        cp_commit();
        cp_wait1();
        __syncthreads();

#pragma unroll 2
        for (int p = 0; p < KT/2; p++) {
            const ulonglong2* kr = (const ulonglong2*)&Kp[buf][p][0];
            ull sc2 = 0ull;
#pragma unroll
            for (int u = 0; u < 16; u++) {
                ulonglong2 kk = kr[u];
                sc2 = fma2(qp[2*u],   kk.x, sc2);
                sc2 = fma2(qp[2*u+1], kk.y, sc2);
            }
            float sA, sB; unpack2(sc2, sA, sB);
            sA *= TEMP; sB *= TEMP;

            float eA = __expf(sA), eB = __expf(sB);
            Z += eA; Z += eB;
            ull eAp = pack2(eA), eBp = pack2(eB);

            int jA = 2*p, jB = 2*p + 1;
            const ulonglong2* va = (const ulonglong2*)&Vs[buf][jA][0];
            const ulonglong2* vbp = (const ulonglong2*)&Vs[buf][jB][0];
#pragma unroll
            for (int c = 0; c < 8; c++) {
                ulonglong2 vv = va[c];
                acc2[2*c]   = fma2(eAp, vv.x, acc2[2*c]);
                acc2[2*c+1] = fma2(eAp, vv.y, acc2[2*c+1]);
            }
#pragma unroll
            for (int c = 0; c < 8; c++) {
                ulonglong2 vv = vbp[c];
                acc2[2*c]   = fma2(eBp, vv.x, acc2[2*c]);
                acc2[2*c+1] = fma2(eBp, vv.y, acc2[2*c+1]);
            }

            // top-4 (strict >, ascending key order)
            int s = t*KT + jA;
            if (sA > t3) {
                if (sA > t1) {
                    if (sA > t0) { t3=t2;i3=i2; t2=t1;i2=i1; t1=t0;i1=i0; t0=sA;i0=s; }
                    else         { t3=t2;i3=i2; t2=t1;i2=i1; t1=sA;i1=s; }
                } else {
                    if (sA > t2) { t3=t2;i3=i2; t2=sA;i2=s; }
                    else         { t3=sA;i3=s; }
                }
            }
            s = t*KT + jB;
            if (sB > t3) {
                if (sB > t1) {
                    if (sB > t0) { t3=t2;i3=i2; t2=t1;i2=i1; t1=t0;i1=i0; t0=sB;i0=s; }
                    else         { t3=t2;i3=i2; t2=t1;i2=i1; t1=sB;i1=s; }
                } else {
                    if (sB > t2) { t3=t2;i3=i2; t2=sB;i2=s; }
                    else         { t3=sB;i3=s; }
                }
            }
        }
        __syncthreads();
    }

    // ---- finalize: subtract top-4 contributions, normalize ----
    float m[32];
#pragma unroll
    for (int i = 0; i < 16; i++) unpack2(acc2[i], m[2*i], m[2*i+1]);

    float e0 = __expf(t0), e1 = __expf(t1), e2v = __expf(t2), e3 = __expf(t3);
    const float* v0 = g_v + ((size_t)bh*2048 + i0)*32;
    const float* v1 = g_v + ((size_t)bh*2048 + i1)*32;
    const float* v2 = g_v + ((size_t)bh*2048 + i2)*32;
    const float* v3 = g_v + ((size_t)bh*2048 + i3)*32;
#pragma unroll
    for (int d = 0; d < 32; d++)
        m[d] -= e0*v0[d] + e1*v1[d] + e2v*v2[d] + e3*v3[d];

    float rZ = 1.0f / Z;
#pragma unroll
    for (int d = 0; d < 32; d++) m[d] *= rZ;

    float* mo = g_msg + ((size_t)(b*2048 + l))*256 + h*32;
#pragma unroll
    for (int i = 0; i < 8; i++)
        ((float4*)mo)[i] = make_float4(m[4*i], m[4*i+1], m[4*i+2], m[4*i+3]);

    int rowi = b*2048 + l;
    float* so = out + SCORE_OFF + rowi*32 + h;   // [row][t][h], t stride 8
    so[0]  = e0*rZ;  so[8]  = e1*rZ;  so[16] = e2v*rZ; so[24] = e3*rZ;
    float* io = out + IDX_OFF + rowi*32 + h;
    io[0]  = (float)i0; io[8]  = (float)i1; io[16] = (float)i2; io[24] = (float)i3;
}

// ---------------------------------------------------------------------------
// 4) Proj GEMM + bias + residual: 64x64 tile, 256 blocks.
// ---------------------------------------------------------------------------
__global__ void __launch_bounds__(256) proj_gemm(const float* __restrict__ Wp,
                                                 const float* __restrict__ bp,
                                                 float* __restrict__ out) {
    __shared__ float As[32][68];
    __shared__ ull   Bs2[32][34];
    int tid = threadIdx.x;
    int r0 = blockIdx.y * 64, n0 = blockIdx.x * 64;
    int tx = tid & 15, ty = tid >> 4;
    float* Bf = (float*)Bs2;

    ull c2[4][2];
#pragma unroll
    for (int i = 0; i < 4; i++) { c2[i][0] = 0ull; c2[i][1] = 0ull; }

    for (int k0 = 0; k0 < 256; k0 += 32) {
#pragma unroll
        for (int r = 0; r < 2; r++) {
            int f = tid + 256*r;
            int mrow = f >> 3, k4 = (f & 7) << 2;
            float4 a = *(const float4*)&g_msg[(r0+mrow)*256 + k0 + k4];
            As[k4+0][mrow]=a.x; As[k4+1][mrow]=a.y; As[k4+2][mrow]=a.z; As[k4+3][mrow]=a.w;
        }
        {
            int f = tid;
            int mcol = f >> 2, k4 = (f & 3) << 3;
            float4 b1 = *(const float4*)&Wp[(n0+mcol)*256 + k0 + k4];
            float4 b2 = *(const float4*)&Wp[(n0+mcol)*256 + k0 + k4 + 4];
            Bf[(k4+0)*68+mcol]=b1.x; Bf[(k4+1)*68+mcol]=b1.y;
            Bf[(k4+2)*68+mcol]=b1.z; Bf[(k4+3)*68+mcol]=b1.w;
            Bf[(k4+4)*68+mcol]=b2.x; Bf[(k4+5)*68+mcol]=b2.y;
            Bf[(k4+6)*68+mcol]=b2.z; Bf[(k4+7)*68+mcol]=b2.w;
        }
        __syncthreads();
#pragma unroll
        for (int kk = 0; kk < 32; kk++) {
            float4 a = *(const float4*)&As[kk][ty*4];
            ull ap0 = pack2(a.x), ap1 = pack2(a.y), ap2 = pack2(a.z), ap3 = pack2(a.w);
#pragma unroll
            for (int u = 0; u < 2; u++) {
                ull b = Bs2[kk][tx + 16*u];
                c2[0][u] = fma2(ap0, b, c2[0][u]);
                c2[1][u] = fma2(ap1, b, c2[1][u]);
                c2[2][u] = fma2(ap2, b, c2[2][u]);
                c2[3][u] = fma2(ap3, b, c2[3][u]);
            }
        }
        __syncthreads();
    }
#pragma unroll
    for (int i = 0; i < 4; i++)
#pragma unroll
        for (int u = 0; u < 2; u++) {
            float lo, hi; unpack2(c2[i][u], lo, hi);
            int row = r0 + ty*4 + i;
            int col = n0 + 2*(tx + 16*u);
            int b = row >> 11, l = row & 2047, h = col >> 5, d = col & 31;
            const float* vres = &g_v[(((b<<3)+h)*2048 + l)*32 + d];
            float2 o;
            o.x = lo + bp[col]   + vres[0];
            o.y = hi + bp[col+1] + vres[1];
            *(float2*)&out[row*256 + col] = o;
        }
}

// ---------------------------------------------------------------------------
extern "C" void kernel_launch(void* const* d_in, const int* in_sizes, int n_in,
                              void* d_out, int out_size) {
    const float* points = (const float*)d_in[0];
    const float* gam    = (const float*)d_in[1];
    const float* bet    = (const float*)d_in[2];
    const float* wqkv   = (const float*)d_in[3];
    const float* wproj  = (const float*)d_in[4];
    const float* bproj  = (const float*)d_in[5];
    float* out = (float*)d_out;

    ln_kernel<<<ROWS, 256>>>(points, gam, bet);
    qkv_gemm <<<dim3(6, 64), 256>>>(wqkv);
    attn_kernel<<<256, 128>>>(out);
    proj_gemm<<<dim3(4, 64), 256>>>(wproj, bproj, out);
}

// round 7
// speedup vs baseline: 1.4717x; 1.0313x over previous
#include <cuda_runtime.h>
#include <math.h>

// Problem constants
#define BB    2
#define NN    2048
#define IND   256
#define DIMV  256
#define HH    8
#define DHH   32
#define ROWS  (BB*NN)          // 4096
#define TEMP  0.17677669529663687f  // fp32(1/sqrt(32))

#define MSG_OFF   0
#define SCORE_OFF 1048576       // ROWS*DIMV
#define IDX_OFF   1179648       // SCORE_OFF + ROWS*4*8

#define NSPLIT 2
#define KEYS_PER_SPLIT 1024

// Scratch (static device memory; no allocations allowed)
__device__ float g_xn [ROWS*IND];
__device__ float g_q  [ROWS*DIMV];   // [b][h][s][d]
__device__ float g_kp [16*1024*32*2];// K pair-interleaved: [bh][s/2][d][s&1]
__device__ float g_v  [ROWS*DIMV];   // [b][h][s][d]
__device__ float g_msg[ROWS*DIMV];   // [row][dim]
// split-KV partials: index p = (split*16 + bh)*2048 + q
__device__ float g_pacc[NSPLIT*16*2048*32];
__device__ float g_pz  [NSPLIT*16*2048];
__device__ float g_pt  [NSPLIT*16*2048*4];
__device__ int   g_pi  [NSPLIT*16*2048*4];

typedef unsigned long long ull;

__device__ __forceinline__ ull fma2(ull a, ull b, ull c) {
    ull d; asm("fma.rn.f32x2 %0,%1,%2,%3;" : "=l"(d) : "l"(a), "l"(b), "l"(c)); return d;
}
__device__ __forceinline__ ull pack2(float x) {
    ull d; unsigned u = __float_as_uint(x);
    asm("mov.b64 %0,{%1,%1};" : "=l"(d) : "r"(u)); return d;
}
__device__ __forceinline__ void unpack2(ull a, float& lo, float& hi) {
    unsigned x, y; asm("mov.b64 {%0,%1},%2;" : "=r"(x), "=r"(y) : "l"(a));
    lo = __uint_as_float(x); hi = __uint_as_float(y);
}
__device__ __forceinline__ void cp16(unsigned dst, const void* src) {
    asm volatile("cp.async.cg.shared.global [%0], [%1], 16;" :: "r"(dst), "l"(src));
}
__device__ __forceinline__ void cp_commit() {
    asm volatile("cp.async.commit_group;");
}
__device__ __forceinline__ void cp_wait1() {
    asm volatile("cp.async.wait_group 1;");
}

// ---------------------------------------------------------------------------
// 1) LayerNorm (unchanged — exactness-critical path)
// ---------------------------------------------------------------------------
__global__ void ln_kernel(const float* __restrict__ x,
                          const float* __restrict__ gam,
                          const float* __restrict__ bet) {
    __shared__ float red[8];
    int row = blockIdx.x, tid = threadIdx.x;
    int w = tid >> 5, ln = tid & 31;
    float v = x[row*IND + tid];

    float s = v;
#pragma unroll
    for (int o = 16; o > 0; o >>= 1) s += __shfl_xor_sync(0xffffffffu, s, o);
    if (ln == 0) red[w] = s;
    __syncthreads();
    float S = 0.f;
#pragma unroll
    for (int i = 0; i < 8; i++) S += red[i];
    float mu = S * (1.0f/IND);

    float d  = v - mu;
    float q  = d * d;
    __syncthreads();
#pragma unroll
    for (int o = 16; o > 0; o >>= 1) q += __shfl_xor_sync(0xffffffffu, q, o);
    if (ln == 0) red[w] = q;
    __syncthreads();
    float Q = 0.f;
#pragma unroll
    for (int i = 0; i < 8; i++) Q += red[i];
    float var = Q * (1.0f/IND);

    float denom = __fsqrt_rn(var + 1e-5f);
    float xh    = __fdiv_rn(d, denom);
    g_xn[row*IND + tid] = xh * gam[tid] + bet[tid];
}

// ---------------------------------------------------------------------------
// 2) QKV GEMM: 64x128 tile, FFMA2 col pairs, register double-buffered loads.
//    K written pair-interleaved.
// ---------------------------------------------------------------------------
__global__ void __launch_bounds__(256) qkv_gemm(const float* __restrict__ W) {
    __shared__ float As[32][68];
    __shared__ ull   Bs2[32][66];
    int tid = threadIdx.x;
    int r0 = blockIdx.y * 64, n0 = blockIdx.x * 128;
    int tx = tid & 15, ty = tid >> 4;
    float* Bf = (float*)Bs2;

    ull c2[4][4];
#pragma unroll
    for (int i = 0; i < 4; i++)
#pragma unroll
        for (int u = 0; u < 4; u++) c2[i][u] = 0ull;

    // addressing for loader lanes
    int am = tid >> 3,            ak4 = (tid & 7) << 2;         // A row/col (+256 second)
    int am2 = (tid + 256) >> 3,   ak42 = ((tid + 256) & 7) << 2;
    float4 a0r, a1r, b0r, b1r, b2r, b3r;

    // prefetch k0 = 0
    a0r = *(const float4*)&g_xn[(r0+am )*256 + ak4 ];
    a1r = *(const float4*)&g_xn[(r0+am2)*256 + ak42];
#pragma unroll
    for (int r = 0; r < 4; r++) {
        int f = tid + 256*r;
        int m = f >> 3, k4 = (f & 7) << 2;
        float4 bv = *(const float4*)&W[(n0+m)*256 + k4];
        if (r == 0) b0r = bv; else if (r == 1) b1r = bv; else if (r == 2) b2r = bv; else b3r = bv;
    }

    for (int k0 = 0; k0 < 256; k0 += 32) {
        // store prefetched tile to smem
        As[ak4 +0][am ]=a0r.x; As[ak4 +1][am ]=a0r.y; As[ak4 +2][am ]=a0r.z; As[ak4 +3][am ]=a0r.w;
        As[ak42+0][am2]=a1r.x; As[ak42+1][am2]=a1r.y; As[ak42+2][am2]=a1r.z; As[ak42+3][am2]=a1r.w;
#pragma unroll
        for (int r = 0; r < 4; r++) {
            int f = tid + 256*r;
            int m = f >> 3, k4 = (f & 7) << 2;
            float4 bv = (r == 0) ? b0r : (r == 1) ? b1r : (r == 2) ? b2r : b3r;
            Bf[(k4+0)*132+m]=bv.x; Bf[(k4+1)*132+m]=bv.y;
            Bf[(k4+2)*132+m]=bv.z; Bf[(k4+3)*132+m]=bv.w;
        }
        __syncthreads();

        // prefetch next tile into registers
        if (k0 + 32 < 256) {
            int kn = k0 + 32;
            a0r = *(const float4*)&g_xn[(r0+am )*256 + kn + ak4 ];
            a1r = *(const float4*)&g_xn[(r0+am2)*256 + kn + ak42];
#pragma unroll
            for (int r = 0; r < 4; r++) {
                int f = tid + 256*r;
                int m = f >> 3, k4 = (f & 7) << 2;
                float4 bv = *(const float4*)&W[(n0+m)*256 + kn + k4];
                if (r == 0) b0r = bv; else if (r == 1) b1r = bv; else if (r == 2) b2r = bv; else b3r = bv;
            }
        }

#pragma unroll
        for (int kk = 0; kk < 32; kk++) {
            float4 a = *(const float4*)&As[kk][ty*4];
            ull ap0 = pack2(a.x), ap1 = pack2(a.y), ap2 = pack2(a.z), ap3 = pack2(a.w);
#pragma unroll
            for (int u = 0; u < 4; u++) {
                ull b = Bs2[kk][tx + 16*u];
                c2[0][u] = fma2(ap0, b, c2[0][u]);
                c2[1][u] = fma2(ap1, b, c2[1][u]);
                c2[2][u] = fma2(ap2, b, c2[2][u]);
                c2[3][u] = fma2(ap3, b, c2[3][u]);
            }
        }
        __syncthreads();
    }
#pragma unroll
    for (int i = 0; i < 4; i++)
#pragma unroll
        for (int u = 0; u < 4; u++) {
            float lo, hi; unpack2(c2[i][u], lo, hi);
            int row = r0 + ty*4 + i;
            int col = n0 + 2*(tx + 16*u);
            int which = col >> 8, h = (col >> 5) & 7, d = col & 31;
            int b = row >> 11, s = row & 2047;
            int bh = (b<<3) + h;
            if (which == 1) {
                float* kp = g_kp + ((((size_t)bh*1024 + (s>>1))*32 + d) << 1) + (s & 1);
                kp[0] = lo; kp[2] = hi;
            } else {
                float* dst = (which == 0) ? g_q : g_v;
                *(float2*)&dst[((size_t)bh*2048 + s)*32 + d] = make_float2(lo, hi);
            }
        }
}

// ---------------------------------------------------------------------------
// 3) Attention (split-KV x2): 512 blocks x 128 threads; block = 128 queries x
//    1024 keys for one (b,h,split). 64-key tiles, cp.async double buffering,
//    4-deep independent score chains. Scores bit-identical to scalar chain.
// ---------------------------------------------------------------------------
#define KT 64
#define NTILE (KEYS_PER_SPLIT/KT)

__global__ void __launch_bounds__(128, 3) attn_kernel() {
    __shared__ ull   Kp[2][KT/2][32];   // 8 KB per stage
    __shared__ float Vs[2][KT][32];     // 8 KB per stage

    int bid   = blockIdx.x;               // 0..511
    int qg    = bid & 15;
    int bh    = (bid >> 4) & 15;
    int split = bid >> 8;                 // 0..1
    int tid   = threadIdx.x;
    int l     = qg*128 + tid;

    // load q, pack each element into both f32x2 lanes
    ull qp[32];
    {
        const float4* qrow = (const float4*)(g_q + ((size_t)bh*2048 + l)*32);
#pragma unroll
        for (int c = 0; c < 8; c++) {
            float4 f = qrow[c];
            qp[4*c+0] = pack2(f.x); qp[4*c+1] = pack2(f.y);
            qp[4*c+2] = pack2(f.z); qp[4*c+3] = pack2(f.w);
        }
    }

    ull acc2[16];
#pragma unroll
    for (int i = 0; i < 16; i++) acc2[i] = 0ull;

    float Z = 0.f;
    float t0 = -3.0e38f, t1 = -3.0e38f, t2 = -3.0e38f, t3 = -3.0e38f;
    int   i0 = 0, i1 = 0, i2 = 0, i3 = 0;

    const char* kg = (const char*)g_kp + (size_t)bh*262144 + (size_t)split*131072;
    const char* vg = (const char*)g_v  + (size_t)bh*262144 + (size_t)split*131072;

    unsigned kbase0 = (unsigned)__cvta_generic_to_shared(&Kp[0][0][0]);
    unsigned kbase1 = (unsigned)__cvta_generic_to_shared(&Kp[1][0][0]);
    unsigned vbase0 = (unsigned)__cvta_generic_to_shared(&Vs[0][0][0]);
    unsigned vbase1 = (unsigned)__cvta_generic_to_shared(&Vs[1][0][0]);

    // prologue: tile 0 -> stage 0
    {
#pragma unroll
        for (int i = 0; i < 4; i++) {
            int c = tid + i*128;
            cp16(kbase0 + c*16, kg + c*16);
            cp16(vbase0 + c*16, vg + c*16);
        }
        cp_commit();
    }

    for (int t = 0; t < NTILE; t++) {
        int buf = t & 1;
        if (t + 1 < NTILE) {
            unsigned kb2 = (buf ? kbase0 : kbase1);
            unsigned vb2 = (buf ? vbase0 : vbase1);
            const char* ks = kg + (size_t)(t+1)*8192;
            const char* vs = vg + (size_t)(t+1)*8192;
#pragma unroll
            for (int i = 0; i < 4; i++) {
                int c = tid + i*128;
                cp16(kb2 + c*16, ks + c*16);
                cp16(vb2 + c*16, vs + c*16);
            }
        }
        cp_commit();
        cp_wait1();
        __syncthreads();

#pragma unroll 4
        for (int p = 0; p < KT/2; p++) {
            const ulonglong2* kr = (const ulonglong2*)&Kp[buf][p][0];
            ull sc2 = 0ull;
#pragma unroll
            for (int u = 0; u < 16; u++) {
                ulonglong2 kk = kr[u];
                sc2 = fma2(qp[2*u],   kk.x, sc2);
                sc2 = fma2(qp[2*u+1], kk.y, sc2);
            }
            float sA, sB; unpack2(sc2, sA, sB);
            sA *= TEMP; sB *= TEMP;

            float eA = __expf(sA), eB = __expf(sB);
            Z += eA; Z += eB;
            ull eAp = pack2(eA), eBp = pack2(eB);

            int jA = 2*p, jB = 2*p + 1;
            const ulonglong2* va  = (const ulonglong2*)&Vs[buf][jA][0];
            const ulonglong2* vbp = (const ulonglong2*)&Vs[buf][jB][0];
#pragma unroll
            for (int c = 0; c < 8; c++) {
                ulonglong2 vv = va[c];
                acc2[2*c]   = fma2(eAp, vv.x, acc2[2*c]);
                acc2[2*c+1] = fma2(eAp, vv.y, acc2[2*c+1]);
            }
#pragma unroll
            for (int c = 0; c < 8; c++) {
                ulonglong2 vv = vbp[c];
                acc2[2*c]   = fma2(eBp, vv.x, acc2[2*c]);
                acc2[2*c+1] = fma2(eBp, vv.y, acc2[2*c+1]);
            }

            int s = split*KEYS_PER_SPLIT + t*KT + jA;
            if (sA > t3) {
                if (sA > t1) {
                    if (sA > t0) { t3=t2;i3=i2; t2=t1;i2=i1; t1=t0;i1=i0; t0=sA;i0=s; }
                    else         { t3=t2;i3=i2; t2=t1;i2=i1; t1=sA;i1=s; }
                } else {
                    if (sA > t2) { t3=t2;i3=i2; t2=sA;i2=s; }
                    else         { t3=sA;i3=s; }
                }
            }
            s = split*KEYS_PER_SPLIT + t*KT + jB;
            if (sB > t3) {
                if (sB > t1) {
                    if (sB > t0) { t3=t2;i3=i2; t2=t1;i2=i1; t1=t0;i1=i0; t0=sB;i0=s; }
                    else         { t3=t2;i3=i2; t2=t1;i2=i1; t1=sB;i1=s; }
                } else {
                    if (sB > t2) { t3=t2;i3=i2; t2=sB;i2=s; }
                    else         { t3=sB;i3=s; }
                }
            }
        }
        __syncthreads();
    }

    // ---- write partials ----
    size_t p = ((size_t)(split*16 + bh))*2048 + l;
    float* pa = g_pacc + p*32;
#pragma unroll
    for (int i = 0; i < 16; i++) {
        float lo, hi; unpack2(acc2[i], lo, hi);
        *(float2*)&pa[2*i] = make_float2(lo, hi);
    }
    g_pz[p] = Z;
    g_pt[p*4+0] = t0; g_pt[p*4+1] = t1; g_pt[p*4+2] = t2; g_pt[p*4+3] = t3;
    g_pi[p*4+0] = i0; g_pi[p*4+1] = i1; g_pi[p*4+2] = i2; g_pi[p*4+3] = i3;
}

// ---------------------------------------------------------------------------
// 3b) Merge: exact top-4 merge (split-0 keys lower index -> >= keeps tie rule)
// ---------------------------------------------------------------------------
__global__ void __launch_bounds__(128) attn_merge(float* __restrict__ out) {
    int idx = blockIdx.x * 128 + threadIdx.x;     // 0..32767
    int bh  = idx >> 11;
    int q   = idx & 2047;
    int b   = bh >> 3, h = bh & 7;

    size_t p0 = (size_t)bh*2048 + q;
    size_t p1 = (size_t)(16 + bh)*2048 + q;

    float T0[4], T1[4]; int I0[4], I1[4];
#pragma unroll
    for (int r = 0; r < 4; r++) {
        T0[r] = g_pt[p0*4+r]; I0[r] = g_pi[p0*4+r];
        T1[r] = g_pt[p1*4+r]; I1[r] = g_pi[p1*4+r];
    }
    float Z = g_pz[p0] + g_pz[p1];

    float ts[4]; int is[4];
    {
        int a = 0, c = 0;
#pragma unroll
        for (int r = 0; r < 4; r++) {
            float s0 = (a < 4) ? T0[a] : -3.3e38f;
            float s1 = (c < 4) ? T1[c] : -3.3e38f;
            if (s0 >= s1) { ts[r] = s0; is[r] = I0[a]; a++; }
            else          { ts[r] = s1; is[r] = I1[c]; c++; }
        }
    }

    float e0 = __expf(ts[0]), e1 = __expf(ts[1]), e2v = __expf(ts[2]), e3 = __expf(ts[3]);
    const float* v0 = g_v + ((size_t)bh*2048 + is[0])*32;
    const float* v1 = g_v + ((size_t)bh*2048 + is[1])*32;
    const float* v2 = g_v + ((size_t)bh*2048 + is[2])*32;
    const float* v3 = g_v + ((size_t)bh*2048 + is[3])*32;

    const float* a0 = g_pacc + p0*32;
    const float* a1 = g_pacc + p1*32;
    float rZ = 1.0f / Z;

    int rowi = b*2048 + q;
    float* mo = g_msg + (size_t)rowi*256 + h*32;
#pragma unroll
    for (int c = 0; c < 8; c++) {
        float4 x0 = *(const float4*)&a0[4*c];
        float4 x1 = *(const float4*)&a1[4*c];
        float4 w0 = *(const float4*)&v0[4*c];
        float4 w1 = *(const float4*)&v1[4*c];
        float4 w2 = *(const float4*)&v2[4*c];
        float4 w3 = *(const float4*)&v3[4*c];
        float4 o;
        o.x = ((x0.x + x1.x) - (e0*w0.x + e1*w1.x + e2v*w2.x + e3*w3.x)) * rZ;
        o.y = ((x0.y + x1.y) - (e0*w0.y + e1*w1.y + e2v*w2.y + e3*w3.y)) * rZ;
        o.z = ((x0.z + x1.z) - (e0*w0.z + e1*w1.z + e2v*w2.z + e3*w3.z)) * rZ;
        o.w = ((x0.w + x1.w) - (e0*w0.w + e1*w1.w + e2v*w2.w + e3*w3.w)) * rZ;
        ((float4*)mo)[c] = o;
    }

    float* so = out + SCORE_OFF + rowi*32 + h;
    so[0]  = e0*rZ;  so[8]  = e1*rZ;  so[16] = e2v*rZ; so[24] = e3*rZ;
    float* io = out + IDX_OFF + rowi*32 + h;
    io[0]  = (float)is[0]; io[8]  = (float)is[1];
    io[16] = (float)is[2]; io[24] = (float)is[3];
}

// ---------------------------------------------------------------------------
// 4) Proj GEMM + bias + residual: 64x64 tile, register double-buffered loads.
// ---------------------------------------------------------------------------
__global__ void __launch_bounds__(256) proj_gemm(const float* __restrict__ Wp,
                                                 const float* __restrict__ bp,
                                                 float* __restrict__ out) {
    __shared__ float As[32][68];
    __shared__ ull   Bs2[32][34];
    int tid = threadIdx.x;
    int r0 = blockIdx.y * 64, n0 = blockIdx.x * 64;
    int tx = tid & 15, ty = tid >> 4;
    float* Bf = (float*)Bs2;

    ull c2[4][2];
#pragma unroll
    for (int i = 0; i < 4; i++) { c2[i][0] = 0ull; c2[i][1] = 0ull; }

    int am = tid >> 3,          ak4 = (tid & 7) << 2;
    int am2 = (tid + 256) >> 3, ak42 = ((tid + 256) & 7) << 2;
    int bm = tid >> 2,          bk8 = (tid & 3) << 3;
    float4 a0r, a1r, b1r, b2r;

    a0r = *(const float4*)&g_msg[(r0+am )*256 + ak4 ];
    a1r = *(const float4*)&g_msg[(r0+am2)*256 + ak42];
    b1r = *(const float4*)&Wp[(n0+bm)*256 + bk8];
    b2r = *(const float4*)&Wp[(n0+bm)*256 + bk8 + 4];

    for (int k0 = 0; k0 < 256; k0 += 32) {
        As[ak4 +0][am ]=a0r.x; As[ak4 +1][am ]=a0r.y; As[ak4 +2][am ]=a0r.z; As[ak4 +3][am ]=a0r.w;
        As[ak42+0][am2]=a1r.x; As[ak42+1][am2]=a1r.y; As[ak42+2][am2]=a1r.z; As[ak42+3][am2]=a1r.w;
        Bf[(bk8+0)*68+bm]=b1r.x; Bf[(bk8+1)*68+bm]=b1r.y;
        Bf[(bk8+2)*68+bm]=b1r.z; Bf[(bk8+3)*68+bm]=b1r.w;
        Bf[(bk8+4)*68+bm]=b2r.x; Bf[(bk8+5)*68+bm]=b2r.y;
        Bf[(bk8+6)*68+bm]=b2r.z; Bf[(bk8+7)*68+bm]=b2r.w;
        __syncthreads();

        if (k0 + 32 < 256) {
            int kn = k0 + 32;
            a0r = *(const float4*)&g_msg[(r0+am )*256 + kn + ak4 ];
            a1r = *(const float4*)&g_msg[(r0+am2)*256 + kn + ak42];
            b1r = *(const float4*)&Wp[(n0+bm)*256 + kn + bk8];
            b2r = *(const float4*)&Wp[(n0+bm)*256 + kn + bk8 + 4];
        }

#pragma unroll
        for (int kk = 0; kk < 32; kk++) {
            float4 a = *(const float4*)&As[kk][ty*4];
            ull ap0 = pack2(a.x), ap1 = pack2(a.y), ap2 = pack2(a.z), ap3 = pack2(a.w);
#pragma unroll
            for (int u = 0; u < 2; u++) {
                ull b = Bs2[kk][tx + 16*u];
                c2[0][u] = fma2(ap0, b, c2[0][u]);
                c2[1][u] = fma2(ap1, b, c2[1][u]);
                c2[2][u] = fma2(ap2, b, c2[2][u]);
                c2[3][u] = fma2(ap3, b, c2[3][u]);
            }
        }
        __syncthreads();
    }
#pragma unroll
    for (int i = 0; i < 4; i++)
#pragma unroll
        for (int u = 0; u < 2; u++) {
            float lo, hi; unpack2(c2[i][u], lo, hi);
            int row = r0 + ty*4 + i;
            int col = n0 + 2*(tx + 16*u);
            int b = row >> 11, l = row & 2047, h = col >> 5, d = col & 31;
            const float* vres = &g_v[(((b<<3)+h)*2048 + l)*32 + d];
            float2 o;
            o.x = lo + bp[col]   + vres[0];
            o.y = hi + bp[col+1] + vres[1];
            *(float2*)&out[row*256 + col] = o;
        }
}

// ---------------------------------------------------------------------------
extern "C" void kernel_launch(void* const* d_in, const int* in_sizes, int n_in,
                              void* d_out, int out_size) {
    const float* points = (const float*)d_in[0];
    const float* gam    = (const float*)d_in[1];
    const float* bet    = (const float*)d_in[2];
    const float* wqkv   = (const float*)d_in[3];
    const float* wproj  = (const float*)d_in[4];
    const float* bproj  = (const float*)d_in[5];
    float* out = (float*)d_out;

    ln_kernel<<<ROWS, 256>>>(points, gam, bet);
    qkv_gemm <<<dim3(6, 64), 256>>>(wqkv);
    attn_kernel<<<512, 128>>>();
    attn_merge<<<256, 128>>>(out);
    proj_gemm<<<dim3(4, 64), 256>>>(wproj, bproj, out);
}